// round 6
// baseline (speedup 1.0000x reference)
#include <cuda_runtime.h>
#include <cuda_fp16.h>
#include <cstdint>

#define NB 16
#define BC 2048

// ---------------------------------------------------------------------------
// Scratch (static device globals)
// ---------------------------------------------------------------------------
__device__ float g_base_thorn[BC * 128];
__device__ float g_A1[BC * 128];
__device__ float g_A2[BC * 128];
__device__ float g_thorn_agg[BC * 128];
__device__ float g_clone_agg[BC * 128];
// Prepacked fp16 B fragments for mma.m16n8k16, nt-pairs adjacent.
// 9 matrices: 0=W_thorn[:H], 1=W_clone[:H], 2=W_clone[H:2H],
//             3=W_thorn[H:2H], 4=W_clone[2H:3H], 5..8=W_agg slices.
// layout [m][ ((ks*8 + ntp)*32 + lane)*4 + j ]  -> 8*8*32*4 = 8192 u32 per matrix
__device__ uint32_t g_Bpack[9][8192];

// ---------------------------------------------------------------------------
// Prepack all weights into fp16 fragment order.
// For ks, ntp, lane (g=l>>2, t4=l&3), j:
//   nt = 2*ntp + (j>>1); k = ks*16 + (j&1)*8 + 2*t4; n = nt*8 + g
//   value = pack_half2(W[k][n], W[k+1][n])
// ---------------------------------------------------------------------------
__global__ void __launch_bounds__(256) prepack_b_kernel(
    const float* __restrict__ W_thorn,
    const float* __restrict__ W_clone,
    const float* __restrict__ W_agg)
{
    int gidx = blockIdx.x * 256 + threadIdx.x;    // 0 .. 9*8192-1
    int m = gidx >> 13;
    int idx = gidx & 8191;
    const float* W;
    switch (m) {
        case 0: W = W_thorn; break;
        case 1: W = W_clone; break;
        case 2: W = W_clone + 16384; break;
        case 3: W = W_thorn + 16384; break;
        case 4: W = W_clone + 32768; break;
        default: W = W_agg + (m - 5) * 16384; break;
    }
    int j    = idx & 3;
    int lane = (idx >> 2) & 31;
    int ntp  = (idx >> 7) & 7;
    int ks   = idx >> 10;               // 0..7
    int t4 = lane & 3, g = lane >> 2;
    int nt = 2 * ntp + (j >> 1);
    int k = ks * 16 + (j & 1) * 8 + 2 * t4;
    int n = nt * 8 + g;
    __half2 h = __floats2half2_rn(W[k * 128 + n], W[(k + 1) * 128 + n]);
    g_Bpack[m][idx] = *(uint32_t*)&h;
}

// ---------------------------------------------------------------------------
// Warp-level MMA accumulate: this warp's 16 rows x 128 cols, K=128.
// A0 points at the warp's first row (row stride 128 floats, fp32 in gmem).
// Bp = prepacked fragment matrix. acc[nt][c] layout:
//   rows r0 = g, r1 = g+8 (relative to A0); cols n0 = nt*8 + 2*t4, n0+1.
// A fragments loaded directly from gmem (float2) with 1-ks-ahead prefetch.
// ---------------------------------------------------------------------------
__device__ __forceinline__ void mma_acc_k128(
    const float* __restrict__ A0,
    const uint32_t* __restrict__ Bp,
    float acc[16][4], int lane)
{
    const int g = lane >> 2, t4 = lane & 3;
    const float* p0 = A0 + g * 128 + 2 * t4;
    const float* p1 = A0 + (g + 8) * 128 + 2 * t4;
    float2 f00 = *(const float2*)(p0);
    float2 f10 = *(const float2*)(p1);
    float2 f01 = *(const float2*)(p0 + 8);
    float2 f11 = *(const float2*)(p1 + 8);
#pragma unroll
    for (int ks = 0; ks < 8; ks++) {
        __half2 h;
        uint32_t a0, a1, a2, a3;
        h = __floats2half2_rn(f00.x, f00.y); a0 = *(uint32_t*)&h;
        h = __floats2half2_rn(f10.x, f10.y); a1 = *(uint32_t*)&h;
        h = __floats2half2_rn(f01.x, f01.y); a2 = *(uint32_t*)&h;
        h = __floats2half2_rn(f11.x, f11.y); a3 = *(uint32_t*)&h;
        if (ks < 7) {
            f00 = *(const float2*)(p0 + 16 * (ks + 1));
            f10 = *(const float2*)(p1 + 16 * (ks + 1));
            f01 = *(const float2*)(p0 + 16 * (ks + 1) + 8);
            f11 = *(const float2*)(p1 + 16 * (ks + 1) + 8);
        }
        const uint32_t* bbase = Bp + ks * 1024 + lane * 4;
#pragma unroll
        for (int ntp = 0; ntp < 8; ntp++) {
            uint4 bb = *(const uint4*)&bbase[ntp * 128];
            asm volatile(
                "mma.sync.aligned.m16n8k16.row.col.f32.f16.f16.f32 "
                "{%0,%1,%2,%3}, {%4,%5,%6,%7}, {%8,%9}, {%0,%1,%2,%3};"
                : "+f"(acc[2 * ntp][0]), "+f"(acc[2 * ntp][1]),
                  "+f"(acc[2 * ntp][2]), "+f"(acc[2 * ntp][3])
                : "r"(a0), "r"(a1), "r"(a2), "r"(a3), "r"(bb.x), "r"(bb.y));
            asm volatile(
                "mma.sync.aligned.m16n8k16.row.col.f32.f16.f16.f32 "
                "{%0,%1,%2,%3}, {%4,%5,%6,%7}, {%8,%9}, {%0,%1,%2,%3};"
                : "+f"(acc[2 * ntp + 1][0]), "+f"(acc[2 * ntp + 1][1]),
                  "+f"(acc[2 * ntp + 1][2]), "+f"(acc[2 * ntp + 1][3])
                : "r"(a0), "r"(a1), "r"(a2), "r"(a3), "r"(bb.z), "r"(bb.w));
        }
    }
}

__device__ __forceinline__ void zero_acc(float acc[16][4]) {
#pragma unroll
    for (int nt = 0; nt < 16; nt++)
#pragma unroll
        for (int c = 0; c < 4; c++) acc[nt][c] = 0.0f;
}

// ---------------------------------------------------------------------------
// Precompute: clone @ {W_thorn[:H], W_clone[:H], W_clone[H:2H]}
// 128 threads = 4 warps, 64 rows per block; grid(32, 3).
// ---------------------------------------------------------------------------
__global__ void __launch_bounds__(128) precompute_kernel(
    const float* __restrict__ clone)
{
    const int tid = threadIdx.x;
    const int warp = tid >> 5;
    const int lane = tid & 31;
    const int y = blockIdx.y;
    const int m0 = blockIdx.x * 64 + warp * 16;

    float* out = (y == 0) ? g_base_thorn : (y == 1) ? g_A1 : g_A2;

    float acc[16][4];
    zero_acc(acc);
    mma_acc_k128(clone + (size_t)m0 * 128, g_Bpack[y], acc, lane);

    const int g = lane >> 2, t4 = lane & 3;
    const int r0 = m0 + g, r1 = r0 + 8;
#pragma unroll
    for (int nt = 0; nt < 16; nt++) {
        const int n0 = nt * 8 + 2 * t4;
        *(float2*)&out[(size_t)r0 * 128 + n0] = make_float2(acc[nt][0], acc[nt][1]);
        *(float2*)&out[(size_t)r1 * 128 + n0] = make_float2(acc[nt][2], acc[nt][3]);
    }
}

// ---------------------------------------------------------------------------
// Relation kernel: one block per (bc, branch). 256 threads = 8 warps.
// No smem A staging: fragments loaded directly from gmem.
// ---------------------------------------------------------------------------
__global__ void __launch_bounds__(256) relation_mma_kernel(
    const float* __restrict__ thorn_rel,
    const float* __restrict__ clone_rel,
    const float* __restrict__ b_thorn,
    const float* __restrict__ b_clone,
    const int* __restrict__ thorn_mask,
    const int* __restrict__ clone_mask)
{
    __shared__ float red[8 * 128];

    const int tid = threadIdx.x;
    const int warp = tid >> 5;
    const int lane = tid & 31;
    const int g = lane >> 2;
    const int t4 = lane & 3;
    const int wrow = warp * 16;
    const int bc = blockIdx.x;
    const int branch = blockIdx.y;
    const int b = bc >> 7;

    const float* rel = branch ? clone_rel : thorn_rel;
    const float* bias = branch ? b_clone : b_thorn;
    const int* mask = branch ? clone_mask : thorn_mask;
    const float* baseCol = branch ? g_A1 : g_base_thorn;
    float* out = branch ? g_clone_agg : g_thorn_agg;

    float acc[16][4];
    zero_acc(acc);
    mma_acc_k128(rel + (size_t)bc * 16384 + (size_t)wrow * 128,
                 g_Bpack[3 + branch], acc, lane);

    // Epilogue: rows r0 = wrow+g, r1 = r0+8; cols n0 = nt*8 + 2*t4.
    const int r0 = wrow + g;
    const int r1 = r0 + 8;
    const float m0 = (float)mask[b * 128 + r0];
    const float m1 = (float)mask[b * 128 + r1];
    const float* rt0p = g_A2 + ((size_t)(b * 128 + r0)) * 128;
    const float* rt1p = g_A2 + ((size_t)(b * 128 + r1)) * 128;

#pragma unroll
    for (int nt = 0; nt < 16; nt++) {
        const int n0 = nt * 8 + 2 * t4;
        float2 bs = *(const float2*)&baseCol[(size_t)bc * 128 + n0];
        float2 bi = *(const float2*)&bias[n0];
        float add0 = bs.x + bi.x;
        float add1 = bs.y + bi.y;
        float x00 = acc[nt][0] + add0;
        float x01 = acc[nt][1] + add1;
        float x10 = acc[nt][2] + add0;
        float x11 = acc[nt][3] + add1;
        if (branch) {
            float2 rt0 = *(const float2*)&rt0p[n0];
            float2 rt1 = *(const float2*)&rt1p[n0];
            x00 += rt0.x; x01 += rt0.y;
            x10 += rt1.x; x11 += rt1.y;
        }
        float c0 = fmaxf(fmaxf(x00, 0.0f) * m0, fmaxf(x10, 0.0f) * m1);
        float c1 = fmaxf(fmaxf(x01, 0.0f) * m0, fmaxf(x11, 0.0f) * m1);
#pragma unroll
        for (int off = 4; off < 32; off <<= 1) {
            c0 = fmaxf(c0, __shfl_xor_sync(0xFFFFFFFFu, c0, off));
            c1 = fmaxf(c1, __shfl_xor_sync(0xFFFFFFFFu, c1, off));
        }
        if (g == 0) {
            red[warp * 128 + n0] = c0;
            red[warp * 128 + n0 + 1] = c1;
        }
    }

    __syncthreads();
    if (tid < 128) {
        float m = 0.0f;
#pragma unroll
        for (int w = 0; w < 8; w++) m = fmaxf(m, red[w * 128 + tid]);
        out[(size_t)bc * 128 + tid] = m;
    }
}

// ---------------------------------------------------------------------------
// Fused final: out = clone + relu([clone|food|thorn_agg|clone_agg] @ W_agg + b)
// K=512 as 4 chained k-slices. 128 threads = 4 warps, 64 rows; grid 32.
// ---------------------------------------------------------------------------
__global__ void __launch_bounds__(128) final_kernel(
    const float* __restrict__ clone,
    const float* __restrict__ food,
    const float* __restrict__ b_agg,
    float* __restrict__ out)
{
    const int tid = threadIdx.x;
    const int warp = tid >> 5;
    const int lane = tid & 31;
    const int m0 = blockIdx.x * 64 + warp * 16;

    float acc[16][4];
    zero_acc(acc);
    mma_acc_k128(clone       + (size_t)m0 * 128, g_Bpack[5], acc, lane);
    mma_acc_k128(food        + (size_t)m0 * 128, g_Bpack[6], acc, lane);
    mma_acc_k128(g_thorn_agg + (size_t)m0 * 128, g_Bpack[7], acc, lane);
    mma_acc_k128(g_clone_agg + (size_t)m0 * 128, g_Bpack[8], acc, lane);

    const int g = lane >> 2, t4 = lane & 3;
    const int r0 = m0 + g, r1 = r0 + 8;
#pragma unroll
    for (int nt = 0; nt < 16; nt++) {
        const int n0 = nt * 8 + 2 * t4;
        float2 bi = *(const float2*)&b_agg[n0];
        float2 c0v = *(const float2*)&clone[(size_t)r0 * 128 + n0];
        float2 c1v = *(const float2*)&clone[(size_t)r1 * 128 + n0];
        float2 o0, o1;
        o0.x = c0v.x + fmaxf(acc[nt][0] + bi.x, 0.0f);
        o0.y = c0v.y + fmaxf(acc[nt][1] + bi.y, 0.0f);
        o1.x = c1v.x + fmaxf(acc[nt][2] + bi.x, 0.0f);
        o1.y = c1v.y + fmaxf(acc[nt][3] + bi.y, 0.0f);
        *(float2*)&out[(size_t)r0 * 128 + n0] = o0;
        *(float2*)&out[(size_t)r1 * 128 + n0] = o1;
    }
}

// ---------------------------------------------------------------------------
// Launch
// ---------------------------------------------------------------------------
extern "C" void kernel_launch(void* const* d_in, const int* in_sizes, int n_in,
                              void* d_out, int out_size)
{
    const float* food       = (const float*)d_in[0];
    const float* thorn_rel  = (const float*)d_in[1];
    const float* clone      = (const float*)d_in[2];
    const float* clone_rel  = (const float*)d_in[3];
    const int*   thorn_mask = (const int*)d_in[4];
    const int*   clone_mask = (const int*)d_in[5];
    const float* W_thorn    = (const float*)d_in[6];
    const float* b_thorn    = (const float*)d_in[7];
    const float* W_clone    = (const float*)d_in[8];
    const float* b_clone    = (const float*)d_in[9];
    const float* W_agg      = (const float*)d_in[10];
    const float* b_agg      = (const float*)d_in[11];
    float* out = (float*)d_out;

    prepack_b_kernel<<<288, 256>>>(W_thorn, W_clone, W_agg);   // 9*8192 threads
    precompute_kernel<<<dim3(32, 3), 128>>>(clone);
    relation_mma_kernel<<<dim3(BC, 2), 256>>>(thorn_rel, clone_rel,
                                              b_thorn, b_clone,
                                              thorn_mask, clone_mask);
    final_kernel<<<32, 128>>>(clone, food, b_agg, out);
}